// round 17
// baseline (speedup 1.0000x reference)
#include <cuda_runtime.h>
#include <cstdint>

#define CIN 64
#define COUT 64
#define NOFFS 26
#define NTAPS 27

// center kernel config (unchanged, round-15/16 form)
#define CTHREADS 128
#define CWPB (CTHREADS / 32)
#define CGP 32

// scatter kernel config: warp-paired N-split, block-level staging
#define STHREADS 128
#define SGRIDX 34                  // 34*26 = 884 blocks ≈ 6/SM capacity (888)
#define BLK_PAIRS 32               // pairs per block iteration (2 MMA groups)

#define BWS_U32 (32 * 32 * 4)                    // 16384 B
#define SBUF_U32 (BLK_PAIRS * 64)                // one buffer: 32 rows x 256B = 2048 u32
#define SMEM_SC_BYTES ((BWS_U32 + 2 * SBUF_U32) * 4)   // 16KB + 16KB = 32768 B
#define SMEM_C_BYTES (BWS_U32 * 4)

typedef uint32_t u32;

// ---- bf16 split helpers -----------------------------------------------------
__device__ __forceinline__ u32 pack_bf16x2(float even, float odd) {
    u32 r;
    asm("cvt.rn.bf16x2.f32 %0, %1, %2;" : "=r"(r) : "f"(odd), "f"(even));
    return r;
}
__device__ __forceinline__ float lo_elem_f(u32 h) { return __uint_as_float(h << 16); }
__device__ __forceinline__ float hi_elem_f(u32 h) { return __uint_as_float(h & 0xffff0000u); }
__device__ __forceinline__ void split2(float e, float o, u32& hp, u32& lp) {
    hp = pack_bf16x2(e, o);
    lp = pack_bf16x2(e - lo_elem_f(hp), o - hi_elem_f(hp));
}

// D += A(16x16 bf16,row) * B(16x8 bf16,col), f32 accumulate
__device__ __forceinline__ void mma_bf16_v(float c[4], u32 a0, u32 a1, u32 a2,
                                           u32 a3, u32 b0, u32 b1) {
    asm volatile(
        "mma.sync.aligned.m16n8k16.row.col.f32.bf16.bf16.f32 "
        "{%0,%1,%2,%3}, {%4,%5,%6,%7}, {%8,%9}, {%0,%1,%2,%3};"
        : "+f"(c[0]), "+f"(c[1]), "+f"(c[2]), "+f"(c[3])
        : "r"(a0), "r"(a1), "r"(a2), "r"(a3), "r"(b0), "r"(b1));
}

// ---- cp.async helpers --------------------------------------------------------
__device__ __forceinline__ u32 smem_u32ptr(const void* p) {
    return (u32)__cvta_generic_to_shared(p);
}
__device__ __forceinline__ void cp_async16(u32 dst, const void* src) {
    asm volatile("cp.async.cg.shared.global [%0], [%1], 16;"
                 :: "r"(dst), "l"(src));
}
__device__ __forceinline__ void cp_commit() {
    asm volatile("cp.async.commit_group;");
}
__device__ __forceinline__ void cp_wait1() {
    asm volatile("cp.async.wait_group 1;");
}

// K-permuted B fragments for tap t (round-15 layout).
template <int NT>
__device__ __forceinline__ void build_b_tiles(uint4* bws,
                                              const float* __restrict__ weight,
                                              int t) {
    for (int idx = threadIdx.x; idx < 32 * 32; idx += NT) {
        int lane = idx & 31, tile = idx >> 5;
        int kt = tile >> 3, nt = tile & 7;
        int n  = nt * 8 + (lane >> 2);
        int k0 = kt * 16 + 4 * (lane & 3);
        const float* wrow = weight + ((long)n * NTAPS + t) * CIN;
        float4 w = __ldg((const float4*)(wrow + k0));
        u32 bh0, bl0, bh1, bl1;
        split2(w.x, w.y, bh0, bl0);
        split2(w.z, w.w, bh1, bl1);
        bws[idx] = make_uint4(bh0, bh1, bl0, bl1);
    }
}

// ----------------------------------------------------------------------------
// Center kernel: out[v] = bias + sp[v] @ Wc  -- plain stores, initializes out.
// ----------------------------------------------------------------------------
__global__ __launch_bounds__(CTHREADS, 4)
void center_kernel(const float* __restrict__ sp,
                   const float* __restrict__ weight,
                   const float* __restrict__ bias,
                   float* __restrict__ out, int n_vox) {
    extern __shared__ u32 smem_raw[];
    uint4* bws = (uint4*)smem_raw;

    build_b_tiles<CTHREADS>(bws, weight, 13);
    __syncthreads();

    const int lane = threadIdx.x & 31;
    const int wid  = threadIdx.x >> 5;
    const int tig  = lane & 3;
    const int g    = lane >> 2;

    const int ngroups = (n_vox + CGP - 1) / CGP;

    for (int grp = blockIdx.x * CWPB + wid; grp < ngroups;
         grp += gridDim.x * CWPB) {
        const int base_v = grp * CGP;

        int v0 = base_v + g;        if (v0 >= n_vox) v0 = n_vox - 1;
        int v1 = base_v + g + 8;    if (v1 >= n_vox) v1 = n_vox - 1;
        int v2 = base_v + g + 16;   if (v2 >= n_vox) v2 = n_vox - 1;
        int v3 = base_v + g + 24;   if (v3 >= n_vox) v3 = n_vox - 1;
        const float* r0 = sp + (long)v0 * CIN;
        const float* r1 = sp + (long)v1 * CIN;
        const float* r2 = sp + (long)v2 * CIN;
        const float* r3 = sp + (long)v3 * CIN;

        float C[2][8][4];
#pragma unroll
        for (int m = 0; m < 2; m++)
#pragma unroll
            for (int nt = 0; nt < 8; nt++) {
                C[m][nt][0] = 0.f; C[m][nt][1] = 0.f;
                C[m][nt][2] = 0.f; C[m][nt][3] = 0.f;
            }

#pragma unroll
        for (int kt = 0; kt < 4; kt++) {
            const int c0 = 16 * kt + 4 * tig;
            float4 f0 = __ldg((const float4*)(r0 + c0));
            float4 f1 = __ldg((const float4*)(r1 + c0));
            float4 e0 = __ldg((const float4*)(r2 + c0));
            float4 e1 = __ldg((const float4*)(r3 + c0));

            u32 x0h, x0l, x1h, x1l, x2h, x2l, x3h, x3l;
            split2(f0.x, f0.y, x0h, x0l);
            split2(f1.x, f1.y, x1h, x1l);
            split2(f0.z, f0.w, x2h, x2l);
            split2(f1.z, f1.w, x3h, x3l);
            u32 y0h, y0l, y1h, y1l, y2h, y2l, y3h, y3l;
            split2(e0.x, e0.y, y0h, y0l);
            split2(e1.x, e1.y, y1h, y1l);
            split2(e0.z, e0.w, y2h, y2l);
            split2(e1.z, e1.w, y3h, y3l);

#pragma unroll
            for (int nt = 0; nt < 8; nt++) {
                uint4 b = bws[(kt * 8 + nt) * 32 + lane];
                mma_bf16_v(C[0][nt], x0h, x1h, x2h, x3h, b.x, b.y);
                mma_bf16_v(C[0][nt], x0l, x1l, x2l, x3l, b.x, b.y);
                mma_bf16_v(C[0][nt], x0h, x1h, x2h, x3h, b.z, b.w);
                mma_bf16_v(C[1][nt], y0h, y1h, y2h, y3h, b.x, b.y);
                mma_bf16_v(C[1][nt], y0l, y1l, y2l, y3l, b.x, b.y);
                mma_bf16_v(C[1][nt], y0h, y1h, y2h, y3h, b.z, b.w);
            }
        }

#pragma unroll
        for (int m = 0; m < 2; m++) {
            int w0 = base_v + 16 * m + g;
            int w1 = w0 + 8;
#pragma unroll
            for (int nt = 0; nt < 8; nt++) {
                float2 b = __ldg((const float2*)bias + nt * 4 + tig);
                if (w0 < n_vox)
                    *(float2*)(out + (long)w0 * COUT + nt * 8 + 2 * tig) =
                        make_float2(C[m][nt][0] + b.x, C[m][nt][1] + b.y);
                if (w1 < n_vox)
                    *(float2*)(out + (long)w1 * COUT + nt * 8 + 2 * tig) =
                        make_float2(C[m][nt][2] + b.x, C[m][nt][3] + b.y);
            }
        }
    }

    cudaTriggerProgrammaticLaunchCompletion();
}

// ----------------------------------------------------------------------------
// Scatter kernel v2: block-level double-buffered cp.async staging of 32 pairs
// per iteration; warp pair (w0,w1) computes group 0 (n-halves 0/1), (w2,w3)
// group 1. C per warp = 4 n-tiles -> ~80 regs -> 6 blocks/SM.
// ----------------------------------------------------------------------------
__global__ __launch_bounds__(STHREADS, 6)
void scatter_kernel(const float* __restrict__ sp,
                    const float* __restrict__ weight,
                    const int2* __restrict__ nei,
                    const int* __restrict__ sizes,
                    float* __restrict__ out, int P) {
    extern __shared__ u32 smem_raw[];
    uint4* bws = (uint4*)smem_raw;
    u32* sbuf  = smem_raw + BWS_U32;        // [2][32 rows][64 u32], XOR-swizzled

    const int o = blockIdx.y;
    const int t = (o < 13) ? o : o + 1;

    build_b_tiles<STHREADS>(bws, weight, t);
    // __syncthreads below (before first compute) covers B-tile visibility.

    const int size = sizes[o];
    if (size <= 0) return;
    const long pair_base = (long)o * P;

    const int tid  = threadIdx.x;
    const int lane = tid & 31;
    const int wid  = tid >> 5;
    const int tig  = lane & 3;
    const int g    = lane >> 2;
    const int grp_in_blk = wid >> 1;        // 0/1: which 16-pair group
    const int nhalf      = wid & 1;         // 0/1: n-tiles [4*nhalf, 4*nhalf+4)

    // staging map: thread covers rows (tid>>4)+8i (i=0..3), 16B chunk tid&15
    const int my_row0  = tid >> 4;          // 0..7
    const int my_chunk = tid & 15;
    const u32 sbuf_base = smem_u32ptr(sbuf);

    const int nblk   = (size + BLK_PAIRS - 1) / BLK_PAIRS;
    const int stride = gridDim.x;
    int it = blockIdx.x;

    // stage iteration `iter`'s 32 rows into buffer b (all 128 threads)
    auto issue_iter = [&](int iter, int b) {
        u32 base = sbuf_base + (u32)b * (SBUF_U32 * 4);
#pragma unroll
        for (int i = 0; i < 4; i++) {
            int row = my_row0 + 8 * i;
            int p = iter * BLK_PAIRS + row;
            if (p >= size) p = size - 1;
            int in = __ldg(&nei[pair_base + p]).y;
            u32 off = row * 256 + ((my_chunk * 16) ^ ((row & 1) * 64));
            cp_async16(base + off, sp + (long)in * CIN + my_chunk * 4);
        }
    };

    if (it < nblk) issue_iter(it, 0);
    cp_commit();

    // PDL: wait for center's stores before any atomicAdd (prologue overlapped)
    cudaGridDependencySynchronize();

    int buf = 0;
    for (; it < nblk; it += stride) {
        const int nx = it + stride;
        if (nx < nblk) issue_iter(nx, buf ^ 1);
        cp_commit();

        cp_wait1();
        __syncthreads();   // staged data (all threads) + B tiles visible

        const int rowbase = grp_in_blk * 16;
        const float* rows = (const float*)(sbuf + buf * SBUF_U32);
        const u32 kxor = (g & 1) * 16;

        float C[4][4];
#pragma unroll
        for (int q = 0; q < 4; q++) {
            C[q][0] = 0.f; C[q][1] = 0.f; C[q][2] = 0.f; C[q][3] = 0.f;
        }

#pragma unroll
        for (int kt = 0; kt < 4; kt++) {
            const u32 kidx = (u32)(16 * kt + 4 * tig) ^ kxor;
            float4 f0 = *(const float4*)(rows + (rowbase + g) * 64 + kidx);
            float4 f1 = *(const float4*)(rows + (rowbase + g + 8) * 64 + kidx);

            u32 x0h, x0l, x1h, x1l, x2h, x2l, x3h, x3l;
            split2(f0.x, f0.y, x0h, x0l);
            split2(f1.x, f1.y, x1h, x1l);
            split2(f0.z, f0.w, x2h, x2l);
            split2(f1.z, f1.w, x3h, x3l);

#pragma unroll
            for (int q = 0; q < 4; q++) {
                int nt = nhalf * 4 + q;
                uint4 b = bws[(kt * 8 + nt) * 32 + lane];
                mma_bf16_v(C[q], x0h, x1h, x2h, x3h, b.x, b.y);  // Ah*Bh
                mma_bf16_v(C[q], x0l, x1l, x2l, x3l, b.x, b.y);  // Al*Bh
                mma_bf16_v(C[q], x0h, x1h, x2h, x3h, b.z, b.w);  // Ah*Bl
            }
        }

        // atomic scatter: this warp's rows rowbase+g, rowbase+g+8;
        // cols nt*8 + 2*tig (nt in this warp's half)
        const int base_p = it * BLK_PAIRS + rowbase;
        int p0 = base_p + g;
        int p1 = base_p + g + 8;
        bool v0 = p0 < size;
        bool v1 = p1 < size;
        int oi0 = __ldg(&nei[pair_base + (v0 ? p0 : size - 1)]).x;
        int oi1 = __ldg(&nei[pair_base + (v1 ? p1 : size - 1)]).x;
        float* o0 = out + (long)oi0 * COUT + 2 * tig;
        float* o1 = out + (long)oi1 * COUT + 2 * tig;
#pragma unroll
        for (int q = 0; q < 4; q++) {
            int nt = nhalf * 4 + q;
            if (v0)
                atomicAdd((float2*)(o0 + nt * 8),
                          make_float2(C[q][0], C[q][1]));
            if (v1)
                atomicAdd((float2*)(o1 + nt * 8),
                          make_float2(C[q][2], C[q][3]));
        }

        __syncthreads();   // all warps done reading buf before it is reused
        buf ^= 1;
    }
}

// ----------------------------------------------------------------------------
extern "C" void kernel_launch(void* const* d_in, const int* in_sizes, int n_in,
                              void* d_out, int out_size) {
    const float* sp     = (const float*)d_in[0];   // [N, 64]
    const float* weight = (const float*)d_in[1];   // [64, 3,3,3, 64]
    const float* bias   = (const float*)d_in[2];   // [64]
    const int2*  nei    = (const int2*)d_in[3];    // [26, P, 2] -> int2 pairs
    const int*   sizes  = (const int*)d_in[4];     // [26]
    float* out = (float*)d_out;

    const int n_vox = in_sizes[0] / CIN;
    const int P     = in_sizes[3] / (NOFFS * 2);

    // 1) center tap + bias with plain stores (initializes out)
    {
        int ngroups = (n_vox + CGP - 1) / CGP;
        int blocks  = (ngroups + CWPB - 1) / CWPB;
        if (blocks > 592) blocks = 592;
        center_kernel<<<blocks, CTHREADS, SMEM_C_BYTES>>>(sp, weight, bias,
                                                          out, n_vox);
    }

    // 2) scatter with PDL: prologue overlaps the center kernel's tail
    {
        cudaLaunchConfig_t cfg = {};
        cfg.gridDim = dim3(SGRIDX, NOFFS, 1);
        cfg.blockDim = dim3(STHREADS, 1, 1);
        cfg.dynamicSmemBytes = SMEM_SC_BYTES;
        cfg.stream = 0;
        cudaLaunchAttribute attr[1];
        attr[0].id = cudaLaunchAttributeProgrammaticStreamSerialization;
        attr[0].val.programmaticStreamSerializationAllowed = 1;
        cfg.attrs = attr;
        cfg.numAttrs = 1;
        cudaLaunchKernelEx(&cfg, scatter_kernel, sp, weight, nei, sizes,
                           out, P);
    }
}